// round 5
// baseline (speedup 1.0000x reference)
#include <cuda_runtime.h>
#include <math.h>

#define NN   8192
#define NT   1024          // threads (one CTA)
#define NB   1024          // bins; one bin per thread
#define EPT  (NN / NT)     // 8 elements per thread

// dynamic smem layout
struct Smem {
    float4 sorted[NN];     // (y, e, theta, c) grouped by bin  : 128 KB
    int    cnt[NB];        //   4 KB
    int    cur[NB];        //   4 KB
    int    start[NB];      //   4 KB (exclusive prefix of cnt)
    double inclE[NB];      //   8 KB (inclusive prefix of bin sum-of-e)
    double sumE[NB];       //   8 KB (raw bin sums)
    int    wti[32];        // warp totals (int scan)
    double wtd[32];        // warp totals (double scan)
    double red[32];        // final reduction
};

__device__ __forceinline__ int bin_of(float y) {
    int b = (int)(y * (1024.0f / 100.0f));
    return min(NB - 1, max(0, b));
}

__global__ void __launch_bounds__(NT, 1)
cox_fused(const float* __restrict__ Y,
          const int*   __restrict__ c,
          const float* __restrict__ logits,
          float* __restrict__ out) {
    extern __shared__ Smem sm[];
    Smem& s = *sm;

    const int t    = threadIdx.x;
    const int lane = t & 31;
    const int wid  = t >> 5;

    // ---- zero bin state ----
    s.cnt[t] = 0;
    s.cur[t] = 0;
    s.sumE[t] = 0.0;
    __syncthreads();

    // ---- phase 1: load, transform, histogram ----
    float4 v[EPT];
    int    vb[EPT];
    #pragma unroll
    for (int k = 0; k < EPT; k++) {
        int i = t + k * NT;
        float y  = Y[i];
        float th = 1.0f / (1.0f + __expf(-logits[i]));
        float e  = __expf(th);
        float cf = (float)c[i];
        v[k]  = make_float4(y, e, th, cf);
        vb[k] = bin_of(y);
        atomicAdd(&s.cnt[vb[k]], 1);
        atomicAdd(&s.sumE[vb[k]], (double)e);
    }
    __syncthreads();

    // ---- phase 2: block scan over 1024 bins (one per thread) ----
    int    myCnt = s.cnt[t];
    double myE   = s.sumE[t];
    int    iv = myCnt;
    double dv = myE;
    #pragma unroll
    for (int o = 1; o < 32; o <<= 1) {
        int    ni = __shfl_up_sync(0xffffffffu, iv, o);
        double nd = __shfl_up_sync(0xffffffffu, dv, o);
        if (lane >= o) { iv += ni; dv += nd; }
    }
    if (lane == 31) { s.wti[wid] = iv; s.wtd[wid] = dv; }
    __syncthreads();
    if (wid == 0) {
        int    wi = s.wti[lane];
        double wd = s.wtd[lane];
        #pragma unroll
        for (int o = 1; o < 32; o <<= 1) {
            int    ni = __shfl_up_sync(0xffffffffu, wi, o);
            double nd = __shfl_up_sync(0xffffffffu, wd, o);
            if (lane >= o) { wi += ni; wd += nd; }
        }
        s.wti[lane] = wi;   // inclusive warp totals
        s.wtd[lane] = wd;
    }
    __syncthreads();
    int    offI = (wid > 0) ? s.wti[wid - 1] : 0;
    double offD = (wid > 0) ? s.wtd[wid - 1] : 0.0;
    s.start[t] = iv + offI - myCnt;   // exclusive start of bin t
    s.inclE[t] = dv + offD;           // inclusive sum-of-e through bin t
    __syncthreads();

    // ---- phase 3: counting-sort scatter into smem ----
    #pragma unroll
    for (int k = 0; k < EPT; k++) {
        int b = vb[k];
        int pos = s.start[b] + atomicAdd(&s.cur[b], 1);
        s.sorted[pos] = v[k];
    }
    __syncthreads();

    const double totalE = s.inclE[NB - 1];

    // ---- phase 4: risk + loss over sorted order (lanes share bin ranges) ----
    float acc = 0.0f;
    #pragma unroll
    for (int k = 0; k < EPT; k++) {
        int sidx = t + k * NT;
        float4 d = s.sorted[sidx];
        int b = bin_of(d.x);
        float r = (float)(totalE - s.inclE[b]);   // strictly-higher bins
        int j0 = s.start[b];
        int j1 = j0 + s.cnt[b];
        float y = d.x;
        for (int j = j0; j < j1; j++) {           // ~8 iters avg, broadcast LDS
            float4 dj = s.sorted[j];
            if (dj.x >= y) r += dj.y;
        }
        acc += d.w * (d.z - __logf(r));           // c*(theta - log risk)
    }

    // ---- reduce + write ----
    double da = (double)acc;
    #pragma unroll
    for (int o = 16; o; o >>= 1)
        da += __shfl_xor_sync(0xffffffffu, da, o);
    if (lane == 0) s.red[wid] = da;
    __syncthreads();
    if (wid == 0) {
        double vv = s.red[lane];
        #pragma unroll
        for (int o = 16; o; o >>= 1)
            vv += __shfl_xor_sync(0xffffffffu, vv, o);
        if (t == 0) out[0] = (float)(-vv / (double)NN);
    }
}

extern "C" void kernel_launch(void* const* d_in, const int* in_sizes, int n_in,
                              void* d_out, int out_size) {
    const float* Y      = (const float*)d_in[0];
    const int*   c      = (const int*)  d_in[1];
    const float* logits = (const float*)d_in[2];
    float* out = (float*)d_out;
    (void)in_sizes; (void)n_in; (void)out_size;

    const int smem = (int)sizeof(Smem);
    cudaFuncSetAttribute(cox_fused, cudaFuncAttributeMaxDynamicSharedMemorySize, smem);
    cox_fused<<<1, NT, smem>>>(Y, c, logits, out);
}

// round 6
// speedup vs baseline: 1.7880x; 1.7880x over previous
#include <cuda_runtime.h>
#include <math.h>

#define NN    8192
#define NCTA  32
#define NT    256
#define NB    256

// ---------------- global scratch (no allocations allowed) ----------------
__device__ float4  g_data[NN];     // (y, e, theta, c) original order
__device__ float4  g_sorted[NN];   // grouped by bin
__device__ int     g_cur[NB];      // scatter cursors
__device__ double  g_acc;
__device__ int     g_done;
// barrier state (self-resetting across graph replays)
__device__ unsigned          g_bcnt = 0;
__device__ volatile unsigned g_bgen = 0;

__device__ __forceinline__ void grid_barrier() {
    __syncthreads();
    if (threadIdx.x == 0) {
        __threadfence();
        unsigned gen = g_bgen;
        if (atomicAdd(&g_bcnt, 1u) == NCTA - 1u) {
            g_bcnt = 0;
            __threadfence();
            g_bgen = gen + 1u;
        } else {
            while (g_bgen == gen) { __nanosleep(32); }
        }
        __threadfence();
    }
    __syncthreads();
}

__device__ __forceinline__ int bin_of(float y) {
    int b = (int)(y * (256.0f / 100.0f));
    return min(NB - 1, max(0, b));
}

__global__ void __launch_bounds__(NT, 1)
cox_fused(const float* __restrict__ Y,
          const int*   __restrict__ c,
          const float* __restrict__ logits,
          float* __restrict__ out) {
    __shared__ int    s_cnt[NB];
    __shared__ double s_sumE[NB];
    __shared__ int    s_start[NB];   // exclusive start of each bin
    __shared__ double s_inclE[NB];   // inclusive prefix of bin sum-of-e
    __shared__ int    s_wti[8];
    __shared__ double s_wtd[8];
    __shared__ double s_red[8];

    const int t    = threadIdx.x;
    const int lane = t & 31;
    const int wid  = t >> 5;
    const int i    = blockIdx.x * NT + t;   // 0..8191, one element per thread

    // zero smem bin state (used in phase B)
    s_cnt[t]  = 0;
    s_sumE[t] = 0.0;

    // ---- phase A: elementwise transform + zero global state ----
    if (blockIdx.x == 0) {
        g_cur[t] = 0;
        if (t == 0) { g_acc = 0.0; g_done = 0; }
    }
    {
        float y  = Y[i];
        float th = 1.0f / (1.0f + __expf(-logits[i]));
        float e  = __expf(th);
        g_data[i] = make_float4(y, e, th, (float)c[i]);
    }
    grid_barrier();

    // ---- phase B: redundant per-CTA histogram + scan, then scatter ----
    #pragma unroll
    for (int k = 0; k < NN / NT; k++) {          // 32 iterations over all data
        float4 d = g_data[t + k * NT];
        int b = bin_of(d.x);
        atomicAdd(&s_cnt[b], 1);
        atomicAdd(&s_sumE[b], (double)d.y);
    }
    __syncthreads();

    // block scan over 256 bins (one per thread)
    int    myCnt = s_cnt[t];
    double myE   = s_sumE[t];
    int    iv = myCnt;
    double dv = myE;
    #pragma unroll
    for (int o = 1; o < 32; o <<= 1) {
        int    ni = __shfl_up_sync(0xffffffffu, iv, o);
        double nd = __shfl_up_sync(0xffffffffu, dv, o);
        if (lane >= o) { iv += ni; dv += nd; }
    }
    if (lane == 31) { s_wti[wid] = iv; s_wtd[wid] = dv; }
    __syncthreads();
    if (wid == 0 && lane < 8) {
        int    wi = s_wti[lane];
        double wd = s_wtd[lane];
        #pragma unroll
        for (int o = 1; o < 8; o <<= 1) {
            int    ni = __shfl_up_sync(0x000000ffu, wi, o);
            double nd = __shfl_up_sync(0x000000ffu, wd, o);
            if (lane >= o) { wi += ni; wd += nd; }
        }
        s_wti[lane] = wi;
        s_wtd[lane] = wd;
    }
    __syncthreads();
    int    offI = (wid > 0) ? s_wti[wid - 1] : 0;
    double offD = (wid > 0) ? s_wtd[wid - 1] : 0.0;
    s_start[t] = iv + offI - myCnt;
    s_inclE[t] = dv + offD;
    __syncthreads();

    // scatter own element via shared global cursors
    {
        float4 d = g_data[i];
        int b = bin_of(d.x);
        int pos = s_start[b] + atomicAdd(&g_cur[b], 1);
        g_sorted[pos] = d;
    }
    grid_barrier();

    // ---- phase C: risk + loss ----
    const double totalE = s_inclE[NB - 1];
    float4 d = g_sorted[i];
    int b = bin_of(d.x);
    float r = (float)(totalE - s_inclE[b]);      // strictly-higher bins
    int j0 = s_start[b];
    int j1 = j0 + s_cnt[b];
    float y = d.x;
    for (int j = j0; j < j1; j++) {              // ~32 iters, L1/L2-hot
        float4 dj = g_sorted[j];
        if (dj.x >= y) r += dj.y;
    }
    float contrib = d.w * (d.z - __logf(r));     // c * (theta - log risk)

    // block reduce -> global accumulate -> last CTA writes out
    double da = (double)contrib;
    #pragma unroll
    for (int o = 16; o; o >>= 1)
        da += __shfl_xor_sync(0xffffffffu, da, o);
    if (lane == 0) s_red[wid] = da;
    __syncthreads();
    if (t == 0) {
        double v = s_red[0];
        #pragma unroll
        for (int w = 1; w < 8; w++) v += s_red[w];
        atomicAdd(&g_acc, v);
        __threadfence();
        int prev = atomicAdd(&g_done, 1);
        if (prev == NCTA - 1) {
            double a = atomicAdd(&g_acc, 0.0);   // ordered read
            out[0] = (float)(-a / (double)NN);
        }
    }
}

extern "C" void kernel_launch(void* const* d_in, const int* in_sizes, int n_in,
                              void* d_out, int out_size) {
    const float* Y      = (const float*)d_in[0];
    const int*   c      = (const int*)  d_in[1];
    const float* logits = (const float*)d_in[2];
    float* out = (float*)d_out;
    (void)in_sizes; (void)n_in; (void)out_size;

    cox_fused<<<NCTA, NT>>>(Y, c, logits, out);
}

// round 7
// speedup vs baseline: 2.7417x; 1.5333x over previous
#include <cuda_runtime.h>
#include <math.h>

#define NN    8192
#define NCTA  32
#define NT    256
#define NB    256

// ---------------- global scratch (zero-init; self-cleaning per run) ------
__device__ float4  g_data[NN];     // (y, e, theta, c) original order
__device__ float4  g_sorted[NN];   // grouped by bin
__device__ int     g_cnt[NB];
__device__ double  g_sumE[NB];
__device__ int     g_cur[NB];
__device__ double  g_acc;
__device__ int     g_done;
__device__ unsigned          g_bcnt;
__device__ volatile unsigned g_bgen;   // monotonic generation (replay-safe)

__device__ __forceinline__ void grid_barrier() {
    __syncthreads();
    if (threadIdx.x == 0) {
        unsigned gen = g_bgen;
        __threadfence();                       // release my CTA's writes
        if (atomicAdd(&g_bcnt, 1u) == NCTA - 1u) {
            g_bcnt = 0;
            __threadfence();
            g_bgen = gen + 1u;
        } else {
            while (g_bgen == gen) { }          // L2-hot spin, no nanosleep
        }
    }
    __syncthreads();
    __threadfence();                           // acquire for all threads
}

__device__ __forceinline__ int bin_of(float y) {
    int b = (int)(y * (256.0f / 100.0f));
    return min(NB - 1, max(0, b));
}

__global__ void __launch_bounds__(NT, 1)
cox_fused(const float* __restrict__ Y,
          const int*   __restrict__ c,
          const float* __restrict__ logits,
          float* __restrict__ out) {
    __shared__ int    s_cnt[NB];
    __shared__ int    s_start[NB];
    __shared__ double s_inclE[NB];
    __shared__ int    s_wti[8];
    __shared__ double s_wtd[8];
    __shared__ double s_red[8];

    const int t    = threadIdx.x;
    const int lane = t & 31;
    const int wid  = t >> 5;
    const int i    = blockIdx.x * NT + t;      // one element per thread

    // ---- phase A: transform own element + distributed global histogram ----
    float4 myd;
    int    myb;
    {
        float y  = Y[i];
        float th = 1.0f / (1.0f + __expf(-logits[i]));
        float e  = __expf(th);
        myd = make_float4(y, e, th, (float)c[i]);
        myb = bin_of(y);
        g_data[i] = myd;
        atomicAdd(&g_cnt[myb], 1);             // spread atomics (256 addrs)
        atomicAdd(&g_sumE[myb], (double)e);    // REDG.F64 (no return)
    }
    grid_barrier();

    // ---- phase B: per-CTA scan of global bins (plain loads), scatter ----
    int    myCnt = g_cnt[t];
    double myE   = g_sumE[t];
    int    iv = myCnt;
    double dv = myE;
    #pragma unroll
    for (int o = 1; o < 32; o <<= 1) {
        int    ni = __shfl_up_sync(0xffffffffu, iv, o);
        double nd = __shfl_up_sync(0xffffffffu, dv, o);
        if (lane >= o) { iv += ni; dv += nd; }
    }
    if (lane == 31) { s_wti[wid] = iv; s_wtd[wid] = dv; }
    __syncthreads();
    if (wid == 0 && lane < 8) {
        int    wi = s_wti[lane];
        double wd = s_wtd[lane];
        #pragma unroll
        for (int o = 1; o < 8; o <<= 1) {
            int    ni = __shfl_up_sync(0x000000ffu, wi, o);
            double nd = __shfl_up_sync(0x000000ffu, wd, o);
            if (lane >= o) { wi += ni; wd += nd; }
        }
        s_wti[lane] = wi;
        s_wtd[lane] = wd;
    }
    __syncthreads();
    {
        int    offI = (wid > 0) ? s_wti[wid - 1] : 0;
        double offD = (wid > 0) ? s_wtd[wid - 1] : 0.0;
        s_cnt[t]   = myCnt;
        s_start[t] = iv + offI - myCnt;        // exclusive start of bin t
        s_inclE[t] = dv + offD;                // inclusive sum-of-e thru bin t
    }
    __syncthreads();

    // scatter own element
    {
        int pos = s_start[myb] + atomicAdd(&g_cur[myb], 1);
        g_sorted[pos] = myd;
    }
    grid_barrier();

    // ---- cleanup global bin state for next replay (after last use) ----
    if (blockIdx.x == 0) g_cnt[t]  = 0;
    if (blockIdx.x == 1) g_sumE[t] = 0.0;
    if (blockIdx.x == 2) g_cur[t]  = 0;

    // ---- phase C: risk + loss (sorted order -> warp-coherent bin loops) ----
    const double totalE = s_inclE[NB - 1];
    float4 d = g_sorted[i];
    int b = bin_of(d.x);
    float r = (float)(totalE - s_inclE[b]);    // strictly-higher bins (f64)
    int j0 = s_start[b];
    int j1 = j0 + s_cnt[b];
    float y = d.x;
    #pragma unroll 4
    for (int j = j0; j < j1; j++) {            // ~32 iters, L2-hot, broadcast
        float4 dj = g_sorted[j];
        if (dj.x >= y) r += dj.y;
    }
    float contrib = d.w * (d.z - __logf(r));   // c * (theta - log risk)

    // ---- reduce -> global accumulate -> last CTA writes + resets ----
    double da = (double)contrib;
    #pragma unroll
    for (int o = 16; o; o >>= 1)
        da += __shfl_xor_sync(0xffffffffu, da, o);
    if (lane == 0) s_red[wid] = da;
    __syncthreads();
    if (t == 0) {
        double v = s_red[0];
        #pragma unroll
        for (int w = 1; w < 8; w++) v += s_red[w];
        atomicAdd(&g_acc, v);
        __threadfence();
        int prev = atomicAdd(&g_done, 1);
        if (prev == NCTA - 1) {
            double a = atomicAdd(&g_acc, 0.0);  // ordered read of final sum
            out[0] = (float)(-a / (double)NN);
            g_acc  = 0.0;                       // self-clean for next replay
            g_done = 0;
        }
    }
}

extern "C" void kernel_launch(void* const* d_in, const int* in_sizes, int n_in,
                              void* d_out, int out_size) {
    const float* Y      = (const float*)d_in[0];
    const int*   c      = (const int*)  d_in[1];
    const float* logits = (const float*)d_in[2];
    float* out = (float*)d_out;
    (void)in_sizes; (void)n_in; (void)out_size;

    cox_fused<<<NCTA, NT>>>(Y, c, logits, out);
}